// round 12
// baseline (speedup 1.0000x reference)
#include <cuda_runtime.h>
#include <cuda_fp16.h>
#include <cstdint>

#define DINLINE __device__ __forceinline__

// ---------------- problem constants ----------------
constexpr int C_    = 32;
constexpr int SP    = 13824;              // 24^3 spatial positions per (b, t)
constexpr long XSTR = 884736;             // 96^3, per-channel stride in x/out
constexpr int MTILES = 432;               // 55296 / 128
constexpr int NTILES = 8;                 // 1024 / 128
constexpr int KCHUNKS = 16;               // 1024 / 64
constexpr int A_TILE = 16384;             // 128 rows x 128B (64 fp16)
constexpr int B_TILE = 16384;             // 128 rows x 128B
constexpr int STAGE_BYTES = A_TILE + B_TILE;          // 32768
constexpr int NSTAGE = 3;
constexpr int SMEM_DYN = NSTAGE * STAGE_BYTES;        // 98304 -> 2 CTAs/SM
constexpr int PT = 132;                   // sCT pitch (floats): conflict-free

// ---------------- scratch (static device globals; no allocation) ----------------
__device__ __align__(1024) __half g_Xh[(size_t)MTILES * KCHUNKS * 8192];
__device__ __align__(1024) __half g_Wh[(size_t)NTILES * KCHUNKS * 8192];

// ---------------- helpers ----------------
DINLINE uint32_t smem_u32(const void* p) {
    uint32_t a;
    asm("{ .reg .u64 t; cvta.to.shared.u64 t, %1; cvt.u32.u64 %0, t; }" : "=r"(a) : "l"(p));
    return a;
}
DINLINE uint32_t swz(uint32_t o) { return o ^ ((o >> 3) & 0x70); }

DINLINE void cp_async16(uint32_t dst, const void* src) {
    asm volatile("cp.async.cg.shared.global [%0], [%1], 16;" :: "r"(dst), "l"(src));
}
#define CP_COMMIT() asm volatile("cp.async.commit_group;" ::: "memory")
#define CP_WAIT1()  asm volatile("cp.async.wait_group 1;" ::: "memory")
#define CP_WAIT0()  asm volatile("cp.async.wait_group 0;" ::: "memory")

DINLINE void ldsm_x4(uint32_t r[4], uint32_t addr) {
    asm volatile("ldmatrix.sync.aligned.m8n8.x4.shared.b16 {%0,%1,%2,%3}, [%4];"
                 : "=r"(r[0]), "=r"(r[1]), "=r"(r[2]), "=r"(r[3]) : "r"(addr));
}
DINLINE void mma16816(float c[4], const uint32_t a[4], uint32_t b0, uint32_t b1) {
    asm volatile(
        "mma.sync.aligned.m16n8k16.row.col.f32.f16.f16.f32 "
        "{%0,%1,%2,%3}, {%4,%5,%6,%7}, {%8,%9}, {%0,%1,%2,%3};"
        : "+f"(c[0]), "+f"(c[1]), "+f"(c[2]), "+f"(c[3])
        : "r"(a[0]), "r"(a[1]), "r"(a[2]), "r"(a[3]), "r"(b0), "r"(b1));
}

// ---------------- prepass: x -> rolled fp16, pre-swizzled A tiles (STS.128 packed) ----------------
__global__ void __launch_bounds__(128) prepass_x(const float* __restrict__ x) {
    __shared__ __align__(16) __half shh[8192];
    const int bx  = blockIdx.x;          // = mt*16 + kc
    const int mt  = bx >> 4;
    const int kc  = bx & 15;
    const int tid = threadIdx.x;
    const int bg  = mt / 108;
    const int b   = bg >> 1;
    const int g   = bg & 1;
    const int sp0 = (mt % 108) * 128;
    const float* xb = x + (size_t)b * C_ * XSTR + sp0 + tid;

    // 8 chunks of 8 consecutive j: per-chunk t is constant, c = j&31 consecutive.
    #pragma unroll
    for (int jc = 0; jc < 8; ++jc) {
        const int j0 = jc * 8;
        const int s  = (kc * 64 + j0) >> 5;          // constant within chunk
        const int t  = (g * 32 + s + 48) & 63;
        const int c0 = j0 & 31;
        const float* src = xb + (size_t)t * SP + (size_t)c0 * XSTR;
        uint32_t pk[4];
        #pragma unroll
        for (int q = 0; q < 4; ++q) {
            const float v0 = __ldcs(src + (size_t)(2 * q) * XSTR);
            const float v1 = __ldcs(src + (size_t)(2 * q + 1) * XSTR);
            const __half2 h2 = __floats2half2_rn(v0, v1);
            pk[q] = *(const uint32_t*)&h2;
        }
        const uint32_t off = swz((uint32_t)tid * 128 + (uint32_t)jc * 16);
        *(uint4*)((char*)shh + off) = make_uint4(pk[0], pk[1], pk[2], pk[3]);
    }
    __syncthreads();
    const uint4* s4h = (const uint4*)shh;
    uint4* dh = (uint4*)((char*)g_Xh + (size_t)bx * A_TILE);
    #pragma unroll
    for (int i = tid; i < 1024; i += 128) { dh[i] = s4h[i]; }
}

// ---------------- prepass: W -> fp16, pre-swizzled 128-row B tiles ----------------
__global__ void __launch_bounds__(128) prepass_w(const float* __restrict__ W) {
    const int bx  = blockIdx.x;          // = nt*16 + kc
    const int nt  = bx >> 4;
    const int kc  = bx & 15;
    const int tid = threadIdx.x;
    const int j   = tid & 63;
    char* dh = (char*)g_Wh + (size_t)bx * B_TILE;
    for (int r = (tid >> 6); r < 128; r += 2) {
        const int o = nt * 128 + r;
        const float v = W[(size_t)o * 1024 + kc * 64 + j];
        const uint32_t off = swz((uint32_t)r * 128 + (uint32_t)j * 2);
        *(__half*)(dh + off) = __float2half_rn(v);
    }
}

// ---------------- GEMM: mma.sync fp16, CTA 128x128, 2 CTAs/SM, seamless pipeline ----------------
DINLINE void issue_loads(int kc, int s, int mt, int nt, int tid, uint32_t smem_base) {
    const char* aH = (const char*)g_Xh + (size_t)(mt * 16 + kc) * A_TILE;
    const char* bH = (const char*)g_Wh + (size_t)(nt * 16 + kc) * B_TILE;
    const uint32_t sAh = smem_base + s * STAGE_BYTES;
    const uint32_t sBh = sAh + A_TILE;
    const uint32_t to = (uint32_t)tid * 16;
    #pragma unroll
    for (int i = 0; i < 4; ++i) {
        const uint32_t o = (uint32_t)i * 4096 + to;
        cp_async16(sAh + o, aH + o);
        cp_async16(sBh + o, bH + o);
    }
}

__global__ void __launch_bounds__(256, 2) gemm_k(const float* __restrict__ bias,
                                                 float* __restrict__ out) {
    extern __shared__ __align__(1024) char smem[];
    const uint32_t smem_base = smem_u32(smem);
    const int tid = threadIdx.x;
    const int l   = tid & 31;
    const int wid = tid >> 5;
    const int wm  = wid & 3;     // m 32-block (0..3)
    const int wn  = wid >> 2;    // n 64-block (0..1)
    const int bx  = blockIdx.x;
    const int nt  = bx & 7;
    const int mt  = bx >> 3;

    // per-lane ldmatrix address components
    uint32_t a_off[2], a_ph[2];
    #pragma unroll
    for (int mb = 0; mb < 2; ++mb) {
        const int row = wm * 32 + mb * 16 + (l & 15);
        a_off[mb] = (uint32_t)row * 128;
        a_ph[mb]  = (uint32_t)(row & 7) * 16;
    }
    const uint32_t a_half = (uint32_t)(l >> 4) * 16;
    const int bmat = l >> 3;
    uint32_t b_off[4], b_ph[4];
    #pragma unroll
    for (int nb2 = 0; nb2 < 4; ++nb2) {
        const int row = wn * 64 + nb2 * 16 + (bmat >> 1) * 8 + (l & 7);
        b_off[nb2] = (uint32_t)row * 128;
        b_ph[nb2]  = (uint32_t)(row & 7) * 16;
    }
    const uint32_t b_half = (uint32_t)(bmat & 1) * 16;

    float acc[2][8][4];
    #pragma unroll
    for (int mb = 0; mb < 2; ++mb)
        #pragma unroll
        for (int nb = 0; nb < 8; ++nb)
            #pragma unroll
            for (int i = 0; i < 4; ++i) acc[mb][nb][i] = 0.f;

    uint32_t ah[2][4], bf[8][2];

    auto load_frags = [&](uint32_t stage_base, uint32_t kbyte) {
        const uint32_t sAh = stage_base;
        const uint32_t sBh = stage_base + A_TILE;
        #pragma unroll
        for (int mb = 0; mb < 2; ++mb)
            ldsm_x4(ah[mb], sAh + a_off[mb] + ((kbyte + a_half) ^ a_ph[mb]));
        #pragma unroll
        for (int nb2 = 0; nb2 < 4; ++nb2) {
            uint32_t r[4];
            ldsm_x4(r, sBh + b_off[nb2] + ((kbyte + b_half) ^ b_ph[nb2]));
            bf[nb2 * 2][0]     = r[0]; bf[nb2 * 2][1]     = r[1];
            bf[nb2 * 2 + 1][0] = r[2]; bf[nb2 * 2 + 1][1] = r[3];
        }
    };

    // prologue: stages 0,1 in flight; frags kk0 of stage 0 in regs
    issue_loads(0, 0, mt, nt, tid, smem_base); CP_COMMIT();
    issue_loads(1, 1, mt, nt, tid, smem_base); CP_COMMIT();
    CP_WAIT1();
    __syncthreads();
    load_frags(smem_base, 0);

    for (int it = 0; it < KCHUNKS; ++it) {
        const uint32_t scb = smem_base + (it % 3) * STAGE_BYTES;

        #pragma unroll
        for (int kk = 0; kk < 4; ++kk) {
            #pragma unroll
            for (int mb = 0; mb < 2; ++mb)
                #pragma unroll
                for (int nb = 0; nb < 8; ++nb)
                    mma16816(acc[mb][nb], ah[mb], bf[nb][0], bf[nb][1]);
            if (kk < 3) load_frags(scb, (uint32_t)(kk + 1) * 32);
        }

        if (it + 1 < KCHUNKS) {
            CP_WAIT0();          // G(it+1) issued a full iteration ago: already landed
            __syncthreads();     // stage (it+2)%3 now free
            load_frags(smem_base + ((it + 1) % 3) * STAGE_BYTES, 0);  // next iter kk0
            if (it + 2 < KCHUNKS) {
                issue_loads(it + 2, (it + 2) % 3, mt, nt, tid, smem_base);
                CP_COMMIT();
            }
        }
    }
    __syncthreads();   // protect smem reuse by epilogue

    // ---------------- epilogue: transposed sCT, conflict-free, 512B streaming stores ----------------
    float* sCT = (float*)smem;           // [128 cols][PT=132 rows]
    const int bg = mt / 108;
    const int b  = bg >> 1;
    const int g  = bg & 1;
    const int sp0 = (mt % 108) * 128;
    float* outB = out + (size_t)b * C_ * XSTR + sp0;

    #pragma unroll
    for (int mb = 0; mb < 2; ++mb) {
        const int row = wm * 32 + mb * 16 + (l >> 2);
        #pragma unroll
        for (int nb = 0; nb < 8; ++nb) {
            const int cc = wn * 64 + nb * 8 + (l & 3) * 2;
            sCT[cc * PT + row]           = acc[mb][nb][0];
            sCT[(cc + 1) * PT + row]     = acc[mb][nb][1];
            sCT[cc * PT + row + 8]       = acc[mb][nb][2];
            sCT[(cc + 1) * PT + row + 8] = acc[mb][nb][3];
        }
    }
    __syncthreads();

    #pragma unroll
    for (int j = 0; j < 16; ++j) {
        const int col = wid * 16 + j;
        const int o   = nt * 128 + col;
        const int sv  = o >> 5;
        const int c   = o & 31;
        const int tp  = (g * 32 + sv + 48) & 63;
        const float bia = __ldg(&bias[o]);
        float4 v = *(float4*)&sCT[col * PT + 4 * l];
        v.x += bia; v.y += bia; v.z += bia; v.w += bia;
        float* dst = outB + (size_t)c * XSTR + (size_t)tp * SP + 4 * l;
        __stcs((float4*)dst, v);
    }
}

// ---------------- host ----------------
extern "C" void kernel_launch(void* const* d_in, const int* in_sizes, int n_in,
                              void* d_out, int out_size) {
    const float* x    = (const float*)d_in[0];
    const float* W    = (const float*)d_in[1];
    const float* bias = (const float*)d_in[2];
    float* out = (float*)d_out;

    cudaFuncSetAttribute(gemm_k, cudaFuncAttributeMaxDynamicSharedMemorySize, SMEM_DYN);

    prepass_x<<<MTILES * KCHUNKS, 128>>>(x);                 // 6912 blocks
    prepass_w<<<NTILES * KCHUNKS, 128>>>(W);                 // 128 blocks
    gemm_k<<<MTILES * NTILES, 256, SMEM_DYN>>>(bias, out);   // 3456 blocks
}